// round 14
// baseline (speedup 1.0000x reference)
#include <cuda_runtime.h>
#include <cuda_fp16.h>
#include <math.h>
#include <stdint.h>

#define B_SZ    4
#define T_SEQ   2048
#define C_DIM   768
#define QKV_DIM 2304
#define N_HEAD  12
#define HD      64
#define M_TOK   (B_SZ * T_SEQ)   // 8192

// scale * log2(e), folded into stored q so flash can use raw ex2
#define CEXP_CONST 0.052057929881742454f

// Scratch (device globals: no allocation allowed)
__device__ __half g_h16[M_TOK * C_DIM];
__device__ __half g_qkv16[M_TOK * QKV_DIM];           // q,k regions used
__device__ __half g_vT16[B_SZ * N_HEAD * HD * T_SEQ]; // V^T, 16-token permuted
__device__ __half g_att16[M_TOK * C_DIM];
__device__ __half g_wT16[QKV_DIM * C_DIM];            // w_attn^T [N][K]
__device__ __half g_wpT16[C_DIM * C_DIM];             // w_proj^T [N][K]

// ---------------------------------------------------------------------------
// PTX helpers
// ---------------------------------------------------------------------------
__device__ __forceinline__ uint32_t smem_u32(const void* p) {
    uint32_t a;
    asm("{ .reg .u64 t; cvta.to.shared.u64 t, %1; cvt.u32.u64 %0, t; }"
        : "=r"(a) : "l"(p));
    return a;
}
#define CP_ASYNC16(dst, src) \
    asm volatile("cp.async.cg.shared.global [%0], [%1], 16;" \
                 :: "r"(dst), "l"(src) : "memory")
#define CP_COMMIT() asm volatile("cp.async.commit_group;" ::: "memory")
#define CP_WAIT(n)  asm volatile("cp.async.wait_group %0;" :: "n"(n) : "memory")

// fp16 m16n8k16 mma, fp32 accumulate.
__device__ __forceinline__ void mma16(float d[4], uint32_t a0, uint32_t a1,
                                      uint32_t a2, uint32_t a3,
                                      uint32_t b0, uint32_t b1) {
    asm volatile(
        "mma.sync.aligned.m16n8k16.row.col.f32.f16.f16.f32 "
        "{%0,%1,%2,%3}, {%4,%5,%6,%7}, {%8,%9}, {%0,%1,%2,%3};"
        : "+f"(d[0]), "+f"(d[1]), "+f"(d[2]), "+f"(d[3])
        : "r"(a0), "r"(a1), "r"(a2), "r"(a3), "r"(b0), "r"(b1));
}
__device__ __forceinline__ uint32_t packh2(float lo, float hi) {
    uint32_t d;
    asm("cvt.rn.f16x2.f32 %0, %1, %2;" : "=r"(d) : "f"(hi), "f"(lo));
    return d;
}
__device__ __forceinline__ uint32_t ex2h2(uint32_t x) {
    uint32_t d;
    asm("ex2.approx.f16x2 %0, %1;" : "=r"(d) : "r"(x));
    return d;
}

// ---------------------------------------------------------------------------
// LayerNorm: warp per row, pure shfl reductions, half2 output.
// ---------------------------------------------------------------------------
__global__ void __launch_bounds__(256)
ln_kernel(const float* __restrict__ x, const float* __restrict__ g,
          const float* __restrict__ b, __half* __restrict__ out) {
    int row = blockIdx.x * 8 + (threadIdx.x >> 5);
    int lane = threadIdx.x & 31;
    const float4* xr = (const float4*)(x + (size_t)row * C_DIM);

    float4 v[6];
    float s = 0.0f;
    #pragma unroll
    for (int i = 0; i < 6; i++) {
        v[i] = xr[lane + 32 * i];
        s += v[i].x + v[i].y + v[i].z + v[i].w;
    }
    #pragma unroll
    for (int o = 16; o; o >>= 1) s += __shfl_xor_sync(0xFFFFFFFFu, s, o);
    float mean = s * (1.0f / C_DIM);

    float sq = 0.0f;
    #pragma unroll
    for (int i = 0; i < 6; i++) {
        float dx = v[i].x - mean, dy = v[i].y - mean;
        float dz = v[i].z - mean, dw = v[i].w - mean;
        sq += dx * dx + dy * dy + dz * dz + dw * dw;
    }
    #pragma unroll
    for (int o = 16; o; o >>= 1) sq += __shfl_xor_sync(0xFFFFFFFFu, sq, o);
    float rstd = rsqrtf(sq * (1.0f / C_DIM) + 1e-5f);

    __half* orow = out + (size_t)row * C_DIM;
    #pragma unroll
    for (int i = 0; i < 6; i++) {
        int j = lane + 32 * i;
        float4 gg = ((const float4*)g)[j];
        float4 bb = ((const float4*)b)[j];
        __half2 h0 = __floats2half2_rn((v[i].x - mean) * rstd * gg.x + bb.x,
                                       (v[i].y - mean) * rstd * gg.y + bb.y);
        __half2 h1 = __floats2half2_rn((v[i].z - mean) * rstd * gg.z + bb.z,
                                       (v[i].w - mean) * rstd * gg.w + bb.w);
        uint2 u = {*(uint32_t*)&h0, *(uint32_t*)&h1};
        *(uint2*)(orow + 4 * j) = u;
    }
}

// ---------------------------------------------------------------------------
// Weight transpose + fp16 convert: W[K,N] -> WT[N,K] fp16 (K contiguous)
// ---------------------------------------------------------------------------
__global__ void transpose_kn(const float* __restrict__ W,
                             __half* __restrict__ WT, int K, int N) {
    __shared__ float t[32][33];
    int n0 = blockIdx.x * 32, k0 = blockIdx.y * 32;
    int x = threadIdx.x, y = threadIdx.y;
    #pragma unroll
    for (int i = 0; i < 32; i += 8)
        t[y + i][x] = W[(size_t)(k0 + y + i) * N + n0 + x];
    __syncthreads();
    #pragma unroll
    for (int i = 0; i < 32; i += 8)
        WT[(size_t)(n0 + y + i) * K + k0 + x] = __float2half(t[x][y + i]);
}

// ---------------------------------------------------------------------------
// fp16 mma GEMM, cp.async 3-stage, K-step 64, tile MT x 128.
// 256 threads = 8 warps (4M x 2N), warp tile (MT/4) x 64.
// MT=128: 2 CTAs/SM, fused branchless A+B loader (measured fastest).
// MT=64: 3 CTAs/SM (proj — kills the 1.3-wave tail).
// MODE 1: fp32 out + bias + residual.
// MODE 2: QKV split -> q (pre-scaled by CEXP_CONST) / k fp16, V -> vT.
// ---------------------------------------------------------------------------
#define GP 16   // words per 32-half block row

template <int MODE, int MT>
__global__ void __launch_bounds__(256, (MT == 64) ? 3 : 2)
gemm_mma(const __half* __restrict__ A, const __half* __restrict__ BT,
         const float* __restrict__ bias, const float* __restrict__ res,
         float* __restrict__ Cout, __half* __restrict__ h2out,
         __half* __restrict__ vT, int N, int K) {
    constexpr int NMT   = MT / 64;          // m16-tiles per warp
    constexpr int A_BLK = MT * GP;
    constexpr int B_BLK = 128 * GP;
    constexpr int STAGE = 2 * (A_BLK + B_BLK);

    extern __shared__ uint32_t smw[];
    uint32_t smb = smem_u32(smw);

    int tid = threadIdx.x, lane = tid & 31, wid = tid >> 5;
    int g = lane >> 2, c = lane & 3;
    int wm = wid & 3, wn = wid >> 2;
    int bm = blockIdx.y * MT, bn = blockIdx.x * 128;

    const __half* Ab = A + (size_t)bm * K;
    const __half* Bb = BT + (size_t)bn * K;

    int iters = K / 64;

    auto load_stage = [&](int s, int ko) {   // ko in halves
        uint32_t ab = smb + (uint32_t)(s * STAGE) * 4;
        uint32_t bb = ab + (uint32_t)(2 * A_BLK) * 4;
        if constexpr (MT == 128) {
            #pragma unroll
            for (int i = 0; i < 4; i++) {
                int idx = tid + i * 256;
                int r = idx >> 3, j = idx & 7;
                int blk = j >> 2, jw = (j & 3) * 4;
                uint32_t so = (uint32_t)(blk * A_BLK + r * GP + jw) * 4;
                int kh = ko + blk * 32 + jw * 2;
                CP_ASYNC16(ab + so, Ab + (size_t)r * K + kh);
                CP_ASYNC16(bb + so, Bb + (size_t)r * K + kh);
            }
        } else {
            constexpr int ACH = MT * 8, TCH = ACH + 1024;
            #pragma unroll
            for (int i = 0; i < TCH / 256; i++) {
                int idx = tid + i * 256;
                if (idx < ACH) {
                    int r = idx >> 3, j = idx & 7;
                    int blk = j >> 2, jw = (j & 3) * 4;
                    CP_ASYNC16(ab + (uint32_t)(blk * A_BLK + r * GP + jw) * 4,
                               Ab + (size_t)r * K + ko + blk * 32 + jw * 2);
                } else {
                    int bidx = idx - ACH;
                    int r = bidx >> 3, j = bidx & 7;
                    int blk = j >> 2, jw = (j & 3) * 4;
                    CP_ASYNC16(bb + (uint32_t)(blk * B_BLK + r * GP + jw) * 4,
                               Bb + (size_t)r * K + ko + blk * 32 + jw * 2);
                }
            }
        }
    };

    load_stage(0, 0);  CP_COMMIT();
    load_stage(1, 64); CP_COMMIT();

    float acc[NMT][8][4] = {};

    for (int it = 0; it < iters; ++it) {
        CP_WAIT(1);
        __syncthreads();

        const uint32_t* stg = smw + (it % 3) * STAGE;

        #pragma unroll
        for (int blk = 0; blk < 2; ++blk) {
            const uint32_t* As = stg + blk * A_BLK;
            const uint32_t* Bs = stg + 2 * A_BLK + blk * B_BLK;

            uint4 alo[NMT], ahi[NMT];
            #pragma unroll
            for (int m = 0; m < NMT; ++m) {
                int r0 = wm * (MT / 4) + m * 16;
                alo[m] = *(const uint4*)&As[(r0 + g) * GP + 4 * c];
                ahi[m] = *(const uint4*)&As[(r0 + g + 8) * GP + 4 * c];
            }

            #pragma unroll
            for (int nt = 0; nt < 8; ++nt) {
                uint4 bq = *(const uint4*)&Bs[(wn * 64 + nt * 8 + g) * GP + 4 * c];
                #pragma unroll
                for (int m = 0; m < NMT; ++m) {
                    mma16(acc[m][nt], alo[m].x, ahi[m].x, alo[m].y, ahi[m].y,
                          bq.x, bq.y);
                    mma16(acc[m][nt], alo[m].z, ahi[m].z, alo[m].w, ahi[m].w,
                          bq.z, bq.w);
                }
            }
        }

        // prefetch AFTER compute (slot (it+2)%3 consumed at it-1; safe past
        // this iter's barrier)
        if (it + 2 < iters) load_stage((it + 2) % 3, (it + 2) * 64);
        CP_COMMIT();
    }

    #pragma unroll
    for (int mt = 0; mt < NMT; ++mt) {
        int r = bm + wm * (MT / 4) + mt * 16 + g;
        #pragma unroll
        for (int nt = 0; nt < 8; ++nt) {
            int col = bn + wn * 64 + nt * 8 + 2 * c;
            float2 bi = *(const float2*)(bias + col);
            float2 o0 = {acc[mt][nt][0] + bi.x, acc[mt][nt][1] + bi.y};
            float2 o1 = {acc[mt][nt][2] + bi.x, acc[mt][nt][3] + bi.y};
            if (MODE == 1) {
                size_t i0 = (size_t)r * N + col;
                size_t i1 = (size_t)(r + 8) * N + col;
                float2 q0 = *(const float2*)(res + i0);
                float2 q1 = *(const float2*)(res + i1);
                o0.x += q0.x; o0.y += q0.y;
                o1.x += q1.x; o1.y += q1.y;
                *(float2*)(Cout + i0) = o0;
                *(float2*)(Cout + i1) = o1;
            } else {   // MODE 2: QKV split
                int cm = col % 192;
                if (cm >= 128) {
                    // V element: scatter fp16 to vT[(b,h)][d][t_perm]
                    int hh = col / 192, d = cm - 128;
                    int bi0 = r >> 11, tb = r & 2047;
                    int tg = tb - g;
                    int p0 = tg + 4 * (g >> 1) + (g & 1);
                    int p1 = p0 + 2;
                    size_t vb = ((size_t)(bi0 * N_HEAD + hh) * HD + d) * T_SEQ;
                    vT[vb + p0]         = __float2half(o0.x);
                    vT[vb + T_SEQ + p0] = __float2half(o0.y);
                    vT[vb + p1]         = __float2half(o1.x);
                    vT[vb + T_SEQ + p1] = __float2half(o1.y);
                } else {
                    if (cm < 64) {   // q: fold softmax scale * log2e
                        o0.x *= CEXP_CONST; o0.y *= CEXP_CONST;
                        o1.x *= CEXP_CONST; o1.y *= CEXP_CONST;
                    }
                    *(__half2*)(h2out + (size_t)r * QKV_DIM + col) =
                        __floats2half2_rn(o0.x, o0.y);
                    *(__half2*)(h2out + (size_t)(r + 8) * QKV_DIM + col) =
                        __floats2half2_rn(o1.x, o1.y);
                }
            }
        }
    }
}

#define GSM(MT) (3 * 2 * ((MT) * GP + 128 * GP) * 4)

// ---------------------------------------------------------------------------
// Flash attention — R10 configuration (measured best): fp16 mma, cp.async
// 2-stage double-buffered K/V, HADD2-tree row sums, prefetch after compute.
// CTA = 128 q-rows of one (b,h); 256 threads = 8 warps x 16 rows.
// q arrives pre-scaled by scale*log2e -> P = ex2(S) directly (f16x2 MUFU).
// P never touches smem; V^T arrives 16-token-permuted (LDS.64 b-frags).
// ---------------------------------------------------------------------------
#define FPQW 48
#define FPVW 40
#define QWW  (128 * FPQW)
#define KVWW (64 * FPQW + 64 * FPVW)
#define FLASH_SMEM ((QWW + 2 * KVWW) * 4)   // 69632 bytes

__global__ void __launch_bounds__(256, 2)
flash_mma(const __half* __restrict__ qkv, const __half* __restrict__ vTg,
          __half* __restrict__ out) {
    extern __shared__ uint32_t smw[];
    uint32_t smb = smem_u32(smw);

    int tid = threadIdx.x, lane = tid & 31, wid = tid >> 5;
    int g = lane >> 2, c = lane & 3;
    int rb = wid * 16;
    int m0 = blockIdx.x * 128;
    int h  = blockIdx.y;
    int bb = blockIdx.z;

    const __half* base = qkv + (size_t)bb * T_SEQ * QKV_DIM + h * (3 * HD);
    const __half* vbase = vTg + (size_t)(bb * N_HEAD + h) * HD * T_SEQ;

    auto load_q = [&]() {
        #pragma unroll
        for (int i = 0; i < 4; i++) {
            int idx = tid + i * 256;
            int r = idx >> 3, j = idx & 7;
            CP_ASYNC16(smb + (uint32_t)(r * FPQW + j * 4) * 4,
                       base + (size_t)(m0 + r) * QKV_DIM + j * 8);
        }
    };
    auto load_kv = [&](int s, int n0) {
        uint32_t kb = smb + (uint32_t)(QWW + s * KVWW) * 4;
        uint32_t vb = kb + (uint32_t)(64 * FPQW) * 4;
        #pragma unroll
        for (int i = 0; i < 2; i++) {
            int idx = tid + i * 256;
            int r = idx >> 3, j = idx & 7;
            CP_ASYNC16(kb + (uint32_t)(r * FPQW + j * 4) * 4,
                       base + (size_t)(n0 + r) * QKV_DIM + 64 + j * 8);
            CP_ASYNC16(vb + (uint32_t)(r * FPVW + j * 4) * 4,
                       vbase + (size_t)r * T_SEQ + n0 + j * 8);
        }
    };

    load_q(); load_kv(0, 0); CP_COMMIT();
    load_kv(1, 64); CP_COMMIT();

    float o[8][4] = {};
    float lrow0 = 0.0f, lrow1 = 0.0f;

    const int NT = T_SEQ / 64;   // 32 tiles
    for (int it = 0; it < NT; ++it) {
        CP_WAIT(1);
        __syncthreads();

        int st = it & 1;
        const uint32_t* Kw = smw + QWW + st * KVWW;
        const uint32_t* Vw = Kw + 64 * FPQW;

        // ---- S = Q @ K^T : 2 blocks of 32 halves, LDS.128 frags ----
        float s[8][4] = {};
        #pragma unroll
        for (int blk = 0; blk < 2; ++blk) {
            int bo = blk * 16 + 4 * c;
            uint4 qlo = *(const uint4*)&smw[(rb + g) * FPQW + bo];
            uint4 qhi = *(const uint4*)&smw[(rb + g + 8) * FPQW + bo];
            #pragma unroll
            for (int nt = 0; nt < 8; ++nt) {
                uint4 kq = *(const uint4*)&Kw[(nt * 8 + g) * FPQW + bo];
                mma16(s[nt], qlo.x, qhi.x, qlo.y, qhi.y, kq.x, kq.y);
                mma16(s[nt], qlo.z, qhi.z, qlo.w, qhi.w, kq.z, kq.w);
            }
        }

        // ---- P = ex2(S) in f16x2; HADD2-tree row sums -> fp32 ----
        uint32_t ph0[8], ph1[8];
        __half2 sum0 = __float2half2_rn(0.0f);
        __half2 sum1 = __float2half2_rn(0.0f);
        #pragma unroll
        for (int nt = 0; nt < 8; ++nt) {
            ph0[nt] = ex2h2(packh2(s[nt][0], s[nt][1]));
            ph1[nt] = ex2h2(packh2(s[nt][2], s[nt][3]));
            sum0 = __hadd2(sum0, *(__half2*)&ph0[nt]);
            sum1 = __hadd2(sum1, *(__half2*)&ph1[nt]);
        }
        float2 f0 = __half22float2(sum0);
        float2 f1 = __half22float2(sum1);
        lrow0 += f0.x + f0.y;
        lrow1 += f1.x + f1.y;

        // ---- O += P @ V : A-frags ready in ph0/ph1, V^T LDS.64 frags ----
        #pragma unroll
        for (int kt = 0; kt < 4; ++kt) {
            uint32_t a0 = ph0[2 * kt];
            uint32_t a1 = ph1[2 * kt];
            uint32_t a2 = ph0[2 * kt + 1];
            uint32_t a3 = ph1[2 * kt + 1];
            int vw = kt * 8 + 2 * c;
            #pragma unroll
            for (int nt = 0; nt < 8; ++nt) {
                uint2 v = *(const uint2*)&Vw[(nt * 8 + g) * FPVW + vw];
                mma16(o[nt], a0, a1, a2, a3, v.x, v.y);
            }
        }

        __syncthreads();   // all warps done with stage st
        if (it + 2 < NT) load_kv(st, (it + 2) * 64);
        CP_COMMIT();
    }

    // epilogue: reduce row sums across the quad once, normalize, store fp16
    lrow0 += __shfl_xor_sync(0xFFFFFFFFu, lrow0, 1);
    lrow0 += __shfl_xor_sync(0xFFFFFFFFu, lrow0, 2);
    lrow1 += __shfl_xor_sync(0xFFFFFFFFu, lrow1, 1);
    lrow1 += __shfl_xor_sync(0xFFFFFFFFu, lrow1, 2);
    float inv0 = 1.0f / lrow0;
    float inv1 = 1.0f / lrow1;
    int row0 = m0 + rb + g;
    int row1 = row0 + 8;
    __half* ob = out + (size_t)bb * T_SEQ * C_DIM + h * HD;
    #pragma unroll
    for (int nt = 0; nt < 8; ++nt) {
        int col = nt * 8 + 2 * c;
        *(__half2*)(ob + (size_t)row0 * C_DIM + col) =
            __floats2half2_rn(o[nt][0] * inv0, o[nt][1] * inv0);
        *(__half2*)(ob + (size_t)row1 * C_DIM + col) =
            __floats2half2_rn(o[nt][2] * inv1, o[nt][3] * inv1);
    }
}

// ---------------------------------------------------------------------------
// Launch
// ---------------------------------------------------------------------------
static void run_pass(const float* x_in, const float* ln_g, const float* ln_b,
                     const __half* wT, const float* b_attn,
                     const __half* wpT, const float* b_proj,
                     float* x_out,
                     __half* hbuf, __half* qkvbuf, __half* vTbuf,
                     __half* attbuf) {
    ln_kernel<<<M_TOK / 8, 256>>>(x_in, ln_g, ln_b, hbuf);

    dim3 gq(QKV_DIM / 128, M_TOK / 128);
    gemm_mma<2, 128><<<gq, 256, GSM(128)>>>(hbuf, wT, b_attn, nullptr,
                                            nullptr, qkvbuf, vTbuf,
                                            QKV_DIM, C_DIM);

    dim3 gf(T_SEQ / 128, N_HEAD, B_SZ);
    flash_mma<<<gf, 256, FLASH_SMEM>>>(qkvbuf, vTbuf, attbuf);

    dim3 gp(C_DIM / 128, M_TOK / 64);
    gemm_mma<1, 64><<<gp, 256, GSM(64)>>>(attbuf, wpT, b_proj, x_in,
                                          x_out, nullptr, nullptr,
                                          C_DIM, C_DIM);
}

extern "C" void kernel_launch(void* const* d_in, const int* in_sizes, int n_in,
                              void* d_out, int out_size) {
    const float* x      = (const float*)d_in[0];
    const float* w_attn = (const float*)d_in[1];
    const float* b_attn = (const float*)d_in[2];
    const float* w_proj = (const float*)d_in[3];
    const float* b_proj = (const float*)d_in[4];
    const float* ln1_g  = (const float*)d_in[5];
    const float* ln1_b  = (const float*)d_in[6];
    const float* ln2_g  = (const float*)d_in[7];
    const float* ln2_b  = (const float*)d_in[8];
    float* out = (float*)d_out;

    cudaFuncSetAttribute(flash_mma,
                         cudaFuncAttributeMaxDynamicSharedMemorySize, FLASH_SMEM);
    cudaFuncSetAttribute((const void*)gemm_mma<2, 128>,
                         cudaFuncAttributeMaxDynamicSharedMemorySize, GSM(128));
    cudaFuncSetAttribute((const void*)gemm_mma<1, 64>,
                         cudaFuncAttributeMaxDynamicSharedMemorySize, GSM(64));

    __half *hbuf, *qkvbuf, *vTbuf, *attbuf, *wT, *wpT;
    cudaGetSymbolAddress((void**)&hbuf, g_h16);
    cudaGetSymbolAddress((void**)&qkvbuf, g_qkv16);
    cudaGetSymbolAddress((void**)&vTbuf, g_vT16);
    cudaGetSymbolAddress((void**)&attbuf, g_att16);
    cudaGetSymbolAddress((void**)&wT, g_wT16);
    cudaGetSymbolAddress((void**)&wpT, g_wpT16);

    dim3 tb(32, 8);
    transpose_kn<<<dim3(QKV_DIM / 32, C_DIM / 32), tb>>>(w_attn, wT, C_DIM, QKV_DIM);
    transpose_kn<<<dim3(C_DIM / 32, C_DIM / 32), tb>>>(w_proj, wpT, C_DIM, C_DIM);

    run_pass(x, ln1_g, ln1_b, wT, b_attn, wpT, b_proj,
             out, hbuf, qkvbuf, vTbuf, attbuf);
    run_pass(out, ln2_g, ln2_b, wT, b_attn, wpT, b_proj,
             out, hbuf, qkvbuf, vTbuf, attbuf);
}

// round 15
// speedup vs baseline: 1.0139x; 1.0139x over previous
#include <cuda_runtime.h>
#include <cuda_fp16.h>
#include <math.h>
#include <stdint.h>

#define B_SZ    4
#define T_SEQ   2048
#define C_DIM   768
#define QKV_DIM 2304
#define N_HEAD  12
#define HD      64
#define M_TOK   (B_SZ * T_SEQ)   // 8192

// scale * log2(e), folded into stored q so flash can use raw ex2
#define CEXP_CONST 0.052057929881742454f
#define H2_ONES 0x3C003C00u      // f16x2 (1.0, 1.0)

// Scratch (device globals: no allocation allowed)
__device__ __half g_h16[M_TOK * C_DIM];
__device__ __half g_qkv16[M_TOK * QKV_DIM];           // q,k regions used
__device__ __half g_vT16[B_SZ * N_HEAD * HD * T_SEQ]; // V^T, 16-token permuted
__device__ __half g_att16[M_TOK * C_DIM];
__device__ __half g_wT16[QKV_DIM * C_DIM];            // w_attn^T [N][K]
__device__ __half g_wpT16[C_DIM * C_DIM];             // w_proj^T [N][K]

// ---------------------------------------------------------------------------
// PTX helpers
// ---------------------------------------------------------------------------
__device__ __forceinline__ uint32_t smem_u32(const void* p) {
    uint32_t a;
    asm("{ .reg .u64 t; cvta.to.shared.u64 t, %1; cvt.u32.u64 %0, t; }"
        : "=r"(a) : "l"(p));
    return a;
}
#define CP_ASYNC16(dst, src) \
    asm volatile("cp.async.cg.shared.global [%0], [%1], 16;" \
                 :: "r"(dst), "l"(src) : "memory")
#define CP_COMMIT() asm volatile("cp.async.commit_group;" ::: "memory")
#define CP_WAIT(n)  asm volatile("cp.async.wait_group %0;" :: "n"(n) : "memory")

// fp16 m16n8k16 mma, fp32 accumulate.
__device__ __forceinline__ void mma16(float d[4], uint32_t a0, uint32_t a1,
                                      uint32_t a2, uint32_t a3,
                                      uint32_t b0, uint32_t b1) {
    asm volatile(
        "mma.sync.aligned.m16n8k16.row.col.f32.f16.f16.f32 "
        "{%0,%1,%2,%3}, {%4,%5,%6,%7}, {%8,%9}, {%0,%1,%2,%3};"
        : "+f"(d[0]), "+f"(d[1]), "+f"(d[2]), "+f"(d[3])
        : "r"(a0), "r"(a1), "r"(a2), "r"(a3), "r"(b0), "r"(b1));
}
__device__ __forceinline__ uint32_t packh2(float lo, float hi) {
    uint32_t d;
    asm("cvt.rn.f16x2.f32 %0, %1, %2;" : "=r"(d) : "f"(hi), "f"(lo));
    return d;
}
__device__ __forceinline__ uint32_t ex2h2(uint32_t x) {
    uint32_t d;
    asm("ex2.approx.f16x2 %0, %1;" : "=r"(d) : "r"(x));
    return d;
}

// ---------------------------------------------------------------------------
// LayerNorm: warp per row, pure shfl reductions, half2 output.
// ---------------------------------------------------------------------------
__global__ void __launch_bounds__(256)
ln_kernel(const float* __restrict__ x, const float* __restrict__ g,
          const float* __restrict__ b, __half* __restrict__ out) {
    int row = blockIdx.x * 8 + (threadIdx.x >> 5);
    int lane = threadIdx.x & 31;
    const float4* xr = (const float4*)(x + (size_t)row * C_DIM);

    float4 v[6];
    float s = 0.0f;
    #pragma unroll
    for (int i = 0; i < 6; i++) {
        v[i] = xr[lane + 32 * i];
        s += v[i].x + v[i].y + v[i].z + v[i].w;
    }
    #pragma unroll
    for (int o = 16; o; o >>= 1) s += __shfl_xor_sync(0xFFFFFFFFu, s, o);
    float mean = s * (1.0f / C_DIM);

    float sq = 0.0f;
    #pragma unroll
    for (int i = 0; i < 6; i++) {
        float dx = v[i].x - mean, dy = v[i].y - mean;
        float dz = v[i].z - mean, dw = v[i].w - mean;
        sq += dx * dx + dy * dy + dz * dz + dw * dw;
    }
    #pragma unroll
    for (int o = 16; o; o >>= 1) sq += __shfl_xor_sync(0xFFFFFFFFu, sq, o);
    float rstd = rsqrtf(sq * (1.0f / C_DIM) + 1e-5f);

    __half* orow = out + (size_t)row * C_DIM;
    #pragma unroll
    for (int i = 0; i < 6; i++) {
        int j = lane + 32 * i;
        float4 gg = ((const float4*)g)[j];
        float4 bb = ((const float4*)b)[j];
        __half2 h0 = __floats2half2_rn((v[i].x - mean) * rstd * gg.x + bb.x,
                                       (v[i].y - mean) * rstd * gg.y + bb.y);
        __half2 h1 = __floats2half2_rn((v[i].z - mean) * rstd * gg.z + bb.z,
                                       (v[i].w - mean) * rstd * gg.w + bb.w);
        uint2 u = {*(uint32_t*)&h0, *(uint32_t*)&h1};
        *(uint2*)(orow + 4 * j) = u;
    }
}

// ---------------------------------------------------------------------------
// Fused weight transposes (both weights in ONE launch):
// W[K,N] -> WT[N,K] fp16. blockIdx.z selects the weight.
// ---------------------------------------------------------------------------
__global__ void transpose_both(const float* __restrict__ Wa,
                               __half* __restrict__ WTa,
                               const float* __restrict__ Wp,
                               __half* __restrict__ WTp) {
    __shared__ float t[32][33];
    const float* W; __half* WT; int K, N;
    if (blockIdx.z == 0) { W = Wa; WT = WTa; K = C_DIM; N = QKV_DIM; }
    else                 { W = Wp; WT = WTp; K = C_DIM; N = C_DIM; }
    if ((int)(blockIdx.x * 32) >= N) return;

    int n0 = blockIdx.x * 32, k0 = blockIdx.y * 32;
    int x = threadIdx.x, y = threadIdx.y;
    #pragma unroll
    for (int i = 0; i < 32; i += 8)
        t[y + i][x] = W[(size_t)(k0 + y + i) * N + n0 + x];
    __syncthreads();
    #pragma unroll
    for (int i = 0; i < 32; i += 8)
        WT[(size_t)(n0 + y + i) * K + k0 + x] = __float2half(t[x][y + i]);
}

// ---------------------------------------------------------------------------
// fp16 mma GEMM, cp.async 3-stage, K-step 64, tile 128 x 128.
// 256 threads = 8 warps (4M x 2N), warp tile 32 x 64. 2 CTAs/SM.
// Fused branchless A+B loader (measured fastest). Prefetch after compute.
// MODE 1: fp32 out + bias + residual.
// MODE 2: QKV split -> q (pre-scaled by CEXP_CONST) / k fp16, V -> vT.
// ---------------------------------------------------------------------------
#define GP 16   // words per 32-half block row
#define A_BLK (128 * GP)
#define B_BLK (128 * GP)
#define STAGE (2 * (A_BLK + B_BLK))
#define GEMM_SMEM (3 * STAGE * 4)   // 98304 bytes

template <int MODE>
__global__ void __launch_bounds__(256, 2)
gemm_mma(const __half* __restrict__ A, const __half* __restrict__ BT,
         const float* __restrict__ bias, const float* __restrict__ res,
         float* __restrict__ Cout, __half* __restrict__ h2out,
         __half* __restrict__ vT, int N, int K) {
    extern __shared__ uint32_t smw[];
    uint32_t smb = smem_u32(smw);

    int tid = threadIdx.x, lane = tid & 31, wid = tid >> 5;
    int g = lane >> 2, c = lane & 3;
    int wm = wid & 3, wn = wid >> 2;
    int bm = blockIdx.y * 128, bn = blockIdx.x * 128;

    const __half* Ab = A + (size_t)bm * K;
    const __half* Bb = BT + (size_t)bn * K;

    int iters = K / 64;

    auto load_stage = [&](int s, int ko) {   // ko in halves
        uint32_t ab = smb + (uint32_t)(s * STAGE) * 4;
        uint32_t bb = ab + (uint32_t)(2 * A_BLK) * 4;
        #pragma unroll
        for (int i = 0; i < 4; i++) {
            int idx = tid + i * 256;
            int r = idx >> 3, j = idx & 7;
            int blk = j >> 2, jw = (j & 3) * 4;
            uint32_t so = (uint32_t)(blk * A_BLK + r * GP + jw) * 4;
            int kh = ko + blk * 32 + jw * 2;
            CP_ASYNC16(ab + so, Ab + (size_t)r * K + kh);
            CP_ASYNC16(bb + so, Bb + (size_t)r * K + kh);
        }
    };

    load_stage(0, 0);  CP_COMMIT();
    load_stage(1, 64); CP_COMMIT();

    float acc[2][8][4] = {};

    for (int it = 0; it < iters; ++it) {
        CP_WAIT(1);
        __syncthreads();

        const uint32_t* stg = smw + (it % 3) * STAGE;

        #pragma unroll
        for (int blk = 0; blk < 2; ++blk) {
            const uint32_t* As = stg + blk * A_BLK;
            const uint32_t* Bs = stg + 2 * A_BLK + blk * B_BLK;

            uint4 alo0 = *(const uint4*)&As[(wm * 32 + g) * GP + 4 * c];
            uint4 ahi0 = *(const uint4*)&As[(wm * 32 + g + 8) * GP + 4 * c];
            uint4 alo1 = *(const uint4*)&As[(wm * 32 + 16 + g) * GP + 4 * c];
            uint4 ahi1 = *(const uint4*)&As[(wm * 32 + 24 + g) * GP + 4 * c];

            #pragma unroll
            for (int nt = 0; nt < 8; ++nt) {
                uint4 bq = *(const uint4*)&Bs[(wn * 64 + nt * 8 + g) * GP + 4 * c];
                mma16(acc[0][nt], alo0.x, ahi0.x, alo0.y, ahi0.y, bq.x, bq.y);
                mma16(acc[0][nt], alo0.z, ahi0.z, alo0.w, ahi0.w, bq.z, bq.w);
                mma16(acc[1][nt], alo1.x, ahi1.x, alo1.y, ahi1.y, bq.x, bq.y);
                mma16(acc[1][nt], alo1.z, ahi1.z, alo1.w, ahi1.w, bq.z, bq.w);
            }
        }

        // prefetch AFTER compute (slot (it+2)%3 consumed at it-1; safe past
        // this iter's barrier)
        if (it + 2 < iters) load_stage((it + 2) % 3, (it + 2) * 64);
        CP_COMMIT();
    }

    #pragma unroll
    for (int mt = 0; mt < 2; ++mt) {
        int r = bm + wm * 32 + mt * 16 + g;
        #pragma unroll
        for (int nt = 0; nt < 8; ++nt) {
            int col = bn + wn * 64 + nt * 8 + 2 * c;
            float2 bi = *(const float2*)(bias + col);
            float2 o0 = {acc[mt][nt][0] + bi.x, acc[mt][nt][1] + bi.y};
            float2 o1 = {acc[mt][nt][2] + bi.x, acc[mt][nt][3] + bi.y};
            if (MODE == 1) {
                size_t i0 = (size_t)r * N + col;
                size_t i1 = (size_t)(r + 8) * N + col;
                float2 q0 = *(const float2*)(res + i0);
                float2 q1 = *(const float2*)(res + i1);
                o0.x += q0.x; o0.y += q0.y;
                o1.x += q1.x; o1.y += q1.y;
                *(float2*)(Cout + i0) = o0;
                *(float2*)(Cout + i1) = o1;
            } else {   // MODE 2: QKV split
                int cm = col % 192;
                if (cm >= 128) {
                    // V element: scatter fp16 to vT[(b,h)][d][t_perm]
                    int hh = col / 192, d = cm - 128;
                    int bi0 = r >> 11, tb = r & 2047;
                    int tg = tb - g;
                    int p0 = tg + 4 * (g >> 1) + (g & 1);
                    int p1 = p0 + 2;
                    size_t vb = ((size_t)(bi0 * N_HEAD + hh) * HD + d) * T_SEQ;
                    vT[vb + p0]         = __float2half(o0.x);
                    vT[vb + T_SEQ + p0] = __float2half(o0.y);
                    vT[vb + p1]         = __float2half(o1.x);
                    vT[vb + T_SEQ + p1] = __float2half(o1.y);
                } else {
                    if (cm < 64) {   // q: fold softmax scale * log2e
                        o0.x *= CEXP_CONST; o0.y *= CEXP_CONST;
                        o1.x *= CEXP_CONST; o1.y *= CEXP_CONST;
                    }
                    *(__half2*)(h2out + (size_t)r * QKV_DIM + col) =
                        __floats2half2_rn(o0.x, o0.y);
                    *(__half2*)(h2out + (size_t)(r + 8) * QKV_DIM + col) =
                        __floats2half2_rn(o1.x, o1.y);
                }
            }
        }
    }
}

// ---------------------------------------------------------------------------
// Flash attention — R13 configuration (measured best flash): fp16 mma,
// cp.async 3-stage K/V ring, ONE barrier/iter, ones-mma row sums.
// CTA = 128 q-rows of one (b,h); 256 threads = 8 warps x 16 rows.
// q arrives pre-scaled by scale*log2e -> P = ex2(S) directly (f16x2 MUFU).
// P never touches smem; V^T arrives 16-token-permuted (LDS.64 b-frags).
// ---------------------------------------------------------------------------
#define FPQW 48
#define FPVW 40
#define QWW  (128 * FPQW)
#define KVWW (64 * FPQW + 64 * FPVW)
#define FLASH_SMEM ((QWW + 3 * KVWW) * 4)   // 92160 bytes

__global__ void __launch_bounds__(256, 2)
flash_mma(const __half* __restrict__ qkv, const __half* __restrict__ vTg,
          __half* __restrict__ out) {
    extern __shared__ uint32_t smw[];
    uint32_t smb = smem_u32(smw);

    int tid = threadIdx.x, lane = tid & 31, wid = tid >> 5;
    int g = lane >> 2, c = lane & 3;
    int rb = wid * 16;
    int m0 = blockIdx.x * 128;
    int h  = blockIdx.y;
    int bb = blockIdx.z;

    const __half* base = qkv + (size_t)bb * T_SEQ * QKV_DIM + h * (3 * HD);
    const __half* vbase = vTg + (size_t)(bb * N_HEAD + h) * HD * T_SEQ;

    auto load_q = [&]() {
        #pragma unroll
        for (int i = 0; i < 4; i++) {
            int idx = tid + i * 256;
            int r = idx >> 3, j = idx & 7;
            CP_ASYNC16(smb + (uint32_t)(r * FPQW + j * 4) * 4,
                       base + (size_t)(m0 + r) * QKV_DIM + j * 8);
        }
    };
    auto load_kv = [&](int s, int n0) {
        uint32_t kb = smb + (uint32_t)(QWW + s * KVWW) * 4;
        uint32_t vb = kb + (uint32_t)(64 * FPQW) * 4;
        #pragma unroll
        for (int i = 0; i < 2; i++) {
            int idx = tid + i * 256;
            int r = idx >> 3, j = idx & 7;
            CP_ASYNC16(kb + (uint32_t)(r * FPQW + j * 4) * 4,
                       base + (size_t)(n0 + r) * QKV_DIM + 64 + j * 8);
            CP_ASYNC16(vb + (uint32_t)(r * FPVW + j * 4) * 4,
                       vbase + (size_t)r * T_SEQ + n0 + j * 8);
        }
    };

    load_q(); load_kv(0, 0); CP_COMMIT();
    load_kv(1, 64); CP_COMMIT();

    float o[8][4] = {};
    float osum[4] = {};   // ones-mma row-sum accumulator

    const int NT = T_SEQ / 64;   // 32 tiles
    for (int it = 0; it < NT; ++it) {
        CP_WAIT(1);
        __syncthreads();

        const uint32_t* Kw = smw + QWW + (it % 3) * KVWW;
        const uint32_t* Vw = Kw + 64 * FPQW;

        // ---- S = Q @ K^T : 2 blocks of 32 halves, LDS.128 frags ----
        float s[8][4] = {};
        #pragma unroll
        for (int blk = 0; blk < 2; ++blk) {
            int bo = blk * 16 + 4 * c;
            uint4 qlo = *(const uint4*)&smw[(rb + g) * FPQW + bo];
            uint4 qhi = *(const uint4*)&smw[(rb + g + 8) * FPQW + bo];
            #pragma unroll
            for (int nt = 0; nt < 8; ++nt) {
                uint4 kq = *(const uint4*)&Kw[(nt * 8 + g) * FPQW + bo];
                mma16(s[nt], qlo.x, qhi.x, qlo.y, qhi.y, kq.x, kq.y);
                mma16(s[nt], qlo.z, qhi.z, qlo.w, qhi.w, kq.z, kq.w);
            }
        }

        // ---- P = ex2(S) in f16x2 (A-operand layout, no extra pack) ----
        uint32_t ph0[8], ph1[8];
        #pragma unroll
        for (int nt = 0; nt < 8; ++nt) {
            ph0[nt] = ex2h2(packh2(s[nt][0], s[nt][1]));
            ph1[nt] = ex2h2(packh2(s[nt][2], s[nt][3]));
        }

        // ---- O += P @ V; row sums += P @ ones (4 extra mma) ----
        #pragma unroll
        for (int kt = 0; kt < 4; ++kt) {
            uint32_t a0 = ph0[2 * kt];
            uint32_t a1 = ph1[2 * kt];
            uint32_t a2 = ph0[2 * kt + 1];
            uint32_t a3 = ph1[2 * kt + 1];
            int vw = kt * 8 + 2 * c;
            #pragma unroll
            for (int nt = 0; nt < 8; ++nt) {
                uint2 v = *(const uint2*)&Vw[(nt * 8 + g) * FPVW + vw];
                mma16(o[nt], a0, a1, a2, a3, v.x, v.y);
            }
            mma16(osum, a0, a1, a2, a3, H2_ONES, H2_ONES);
        }

        // prefetch tile it+2 into slot (it+2)%3 (freed at it-1)
        if (it + 2 < NT) load_kv((it + 2) % 3, (it + 2) * 64);
        CP_COMMIT();
    }

    // epilogue: osum[0]/osum[2] are FULL row sums (mma gathered the quad)
    float inv0 = 1.0f / osum[0];
    float inv1 = 1.0f / osum[2];
    int row0 = m0 + rb + g;
    int row1 = row0 + 8;
    __half* ob = out + (size_t)bb * T_SEQ * C_DIM + h * HD;
    #pragma unroll
    for (int nt = 0; nt < 8; ++nt) {
        int col = nt * 8 + 2 * c;
        *(__half2*)(ob + (size_t)row0 * C_DIM + col) =
            __floats2half2_rn(o[nt][0] * inv0, o[nt][1] * inv0);
        *(__half2*)(ob + (size_t)row1 * C_DIM + col) =
            __floats2half2_rn(o[nt][2] * inv1, o[nt][3] * inv1);
    }
}

// ---------------------------------------------------------------------------
// Launch
// ---------------------------------------------------------------------------
static void run_pass(const float* x_in, const float* ln_g, const float* ln_b,
                     const __half* wT, const float* b_attn,
                     const __half* wpT, const float* b_proj,
                     float* x_out,
                     __half* hbuf, __half* qkvbuf, __half* vTbuf,
                     __half* attbuf) {
    ln_kernel<<<M_TOK / 8, 256>>>(x_in, ln_g, ln_b, hbuf);

    dim3 gq(QKV_DIM / 128, M_TOK / 128);
    gemm_mma<2><<<gq, 256, GEMM_SMEM>>>(hbuf, wT, b_attn, nullptr,
                                        nullptr, qkvbuf, vTbuf,
                                        QKV_DIM, C_DIM);

    dim3 gf(T_SEQ / 128, N_HEAD, B_SZ);
    flash_mma<<<gf, 256, FLASH_SMEM>>>(qkvbuf, vTbuf, attbuf);

    dim3 gp(C_DIM / 128, M_TOK / 128);
    gemm_mma<1><<<gp, 256, GEMM_SMEM>>>(attbuf, wpT, b_proj, x_in,
                                        x_out, nullptr, nullptr,
                                        C_DIM, C_DIM);
}

extern "C" void kernel_launch(void* const* d_in, const int* in_sizes, int n_in,
                              void* d_out, int out_size) {
    const float* x      = (const float*)d_in[0];
    const float* w_attn = (const float*)d_in[1];
    const float* b_attn = (const float*)d_in[2];
    const float* w_proj = (const float*)d_in[3];
    const float* b_proj = (const float*)d_in[4];
    const float* ln1_g  = (const float*)d_in[5];
    const float* ln1_b  = (const float*)d_in[6];
    const float* ln2_g  = (const float*)d_in[7];
    const float* ln2_b  = (const float*)d_in[8];
    float* out = (float*)d_out;

    cudaFuncSetAttribute(flash_mma,
                         cudaFuncAttributeMaxDynamicSharedMemorySize, FLASH_SMEM);
    cudaFuncSetAttribute((const void*)gemm_mma<1>,
                         cudaFuncAttributeMaxDynamicSharedMemorySize, GEMM_SMEM);
    cudaFuncSetAttribute((const void*)gemm_mma<2>,
                         cudaFuncAttributeMaxDynamicSharedMemorySize, GEMM_SMEM);

    __half *hbuf, *qkvbuf, *vTbuf, *attbuf, *wT, *wpT;
    cudaGetSymbolAddress((void**)&hbuf, g_h16);
    cudaGetSymbolAddress((void**)&qkvbuf, g_qkv16);
    cudaGetSymbolAddress((void**)&vTbuf, g_vT16);
    cudaGetSymbolAddress((void**)&attbuf, g_att16);
    cudaGetSymbolAddress((void**)&wT, g_wT16);
    cudaGetSymbolAddress((void**)&wpT, g_wpT16);

    // Both weight transposes in one launch (z=0: w_attn, z=1: w_proj)
    dim3 tb(32, 8);
    dim3 tg(QKV_DIM / 32, C_DIM / 32, 2);
    transpose_both<<<tg, tb>>>(w_attn, wT, w_proj, wpT);

    run_pass(x, ln1_g, ln1_b, wT, b_attn, wpT, b_proj,
             out, hbuf, qkvbuf, vTbuf, attbuf);
    run_pass(out, ln2_g, ln2_b, wT, b_attn, wpT, b_proj,
             out, hbuf, qkvbuf, vTbuf, attbuf);
}

// round 16
// speedup vs baseline: 1.0675x; 1.0529x over previous
#include <cuda_runtime.h>
#include <cuda_fp16.h>
#include <math.h>
#include <stdint.h>

#define B_SZ    4
#define T_SEQ   2048
#define C_DIM   768
#define QKV_DIM 2304
#define N_HEAD  12
#define HD      64
#define M_TOK   (B_SZ * T_SEQ)   // 8192

// scale * log2(e), folded into stored q so flash can use raw ex2
#define CEXP_CONST 0.052057929881742454f
#define H2_ONES 0x3C003C00u      // f16x2 (1.0, 1.0)

// Scratch (device globals: no allocation allowed)
__device__ __half g_h16[M_TOK * C_DIM];
__device__ __half g_qkv16[M_TOK * QKV_DIM];           // q,k regions used
__device__ __half g_vT16[B_SZ * N_HEAD * HD * T_SEQ]; // V^T, 16-token permuted
__device__ __half g_att16[M_TOK * C_DIM];
__device__ __half g_wT16[QKV_DIM * C_DIM];            // w_attn^T [N][K]
__device__ __half g_wpT16[C_DIM * C_DIM];             // w_proj^T [N][K]

// ---------------------------------------------------------------------------
// PTX helpers
// ---------------------------------------------------------------------------
__device__ __forceinline__ uint32_t smem_u32(const void* p) {
    uint32_t a;
    asm("{ .reg .u64 t; cvta.to.shared.u64 t, %1; cvt.u32.u64 %0, t; }"
        : "=r"(a) : "l"(p));
    return a;
}
#define CP_ASYNC16(dst, src) \
    asm volatile("cp.async.cg.shared.global [%0], [%1], 16;" \
                 :: "r"(dst), "l"(src) : "memory")
#define CP_COMMIT() asm volatile("cp.async.commit_group;" ::: "memory")
#define CP_WAIT(n)  asm volatile("cp.async.wait_group %0;" :: "n"(n) : "memory")

// fp16 m16n8k16 mma, fp32 accumulate.
__device__ __forceinline__ void mma16(float d[4], uint32_t a0, uint32_t a1,
                                      uint32_t a2, uint32_t a3,
                                      uint32_t b0, uint32_t b1) {
    asm volatile(
        "mma.sync.aligned.m16n8k16.row.col.f32.f16.f16.f32 "
        "{%0,%1,%2,%3}, {%4,%5,%6,%7}, {%8,%9}, {%0,%1,%2,%3};"
        : "+f"(d[0]), "+f"(d[1]), "+f"(d[2]), "+f"(d[3])
        : "r"(a0), "r"(a1), "r"(a2), "r"(a3), "r"(b0), "r"(b1));
}
__device__ __forceinline__ uint32_t packh2(float lo, float hi) {
    uint32_t d;
    asm("cvt.rn.f16x2.f32 %0, %1, %2;" : "=r"(d) : "f"(hi), "f"(lo));
    return d;
}
__device__ __forceinline__ uint32_t ex2h2(uint32_t x) {
    uint32_t d;
    asm("ex2.approx.f16x2 %0, %1;" : "=r"(d) : "r"(x));
    return d;
}

// ---------------------------------------------------------------------------
// LayerNorm: warp per row, pure shfl reductions, half2 output.
// ---------------------------------------------------------------------------
__global__ void __launch_bounds__(256)
ln_kernel(const float* __restrict__ x, const float* __restrict__ g,
          const float* __restrict__ b, __half* __restrict__ out) {
    int row = blockIdx.x * 8 + (threadIdx.x >> 5);
    int lane = threadIdx.x & 31;
    const float4* xr = (const float4*)(x + (size_t)row * C_DIM);

    float4 v[6];
    float s = 0.0f;
    #pragma unroll
    for (int i = 0; i < 6; i++) {
        v[i] = xr[lane + 32 * i];
        s += v[i].x + v[i].y + v[i].z + v[i].w;
    }
    #pragma unroll
    for (int o = 16; o; o >>= 1) s += __shfl_xor_sync(0xFFFFFFFFu, s, o);
    float mean = s * (1.0f / C_DIM);

    float sq = 0.0f;
    #pragma unroll
    for (int i = 0; i < 6; i++) {
        float dx = v[i].x - mean, dy = v[i].y - mean;
        float dz = v[i].z - mean, dw = v[i].w - mean;
        sq += dx * dx + dy * dy + dz * dz + dw * dw;
    }
    #pragma unroll
    for (int o = 16; o; o >>= 1) sq += __shfl_xor_sync(0xFFFFFFFFu, sq, o);
    float rstd = rsqrtf(sq * (1.0f / C_DIM) + 1e-5f);

    __half* orow = out + (size_t)row * C_DIM;
    #pragma unroll
    for (int i = 0; i < 6; i++) {
        int j = lane + 32 * i;
        float4 gg = ((const float4*)g)[j];
        float4 bb = ((const float4*)b)[j];
        __half2 h0 = __floats2half2_rn((v[i].x - mean) * rstd * gg.x + bb.x,
                                       (v[i].y - mean) * rstd * gg.y + bb.y);
        __half2 h1 = __floats2half2_rn((v[i].z - mean) * rstd * gg.z + bb.z,
                                       (v[i].w - mean) * rstd * gg.w + bb.w);
        uint2 u = {*(uint32_t*)&h0, *(uint32_t*)&h1};
        *(uint2*)(orow + 4 * j) = u;
    }
}

// ---------------------------------------------------------------------------
// Fused weight transposes (both weights in ONE launch):
// W[K,N] -> WT[N,K] fp16. blockIdx.z selects the weight.
// ---------------------------------------------------------------------------
__global__ void transpose_both(const float* __restrict__ Wa,
                               __half* __restrict__ WTa,
                               const float* __restrict__ Wp,
                               __half* __restrict__ WTp) {
    __shared__ float t[32][33];
    const float* W; __half* WT; int K, N;
    if (blockIdx.z == 0) { W = Wa; WT = WTa; K = C_DIM; N = QKV_DIM; }
    else                 { W = Wp; WT = WTp; K = C_DIM; N = C_DIM; }
    if ((int)(blockIdx.x * 32) >= N) return;

    int n0 = blockIdx.x * 32, k0 = blockIdx.y * 32;
    int x = threadIdx.x, y = threadIdx.y;
    #pragma unroll
    for (int i = 0; i < 32; i += 8)
        t[y + i][x] = W[(size_t)(k0 + y + i) * N + n0 + x];
    __syncthreads();
    #pragma unroll
    for (int i = 0; i < 32; i += 8)
        WT[(size_t)(n0 + y + i) * K + k0 + x] = __float2half(t[x][y + i]);
}

// ---------------------------------------------------------------------------
// fp16 mma GEMM, cp.async 3-stage, K-step 64, tile 128 x 128.
// 256 threads = 8 warps (4M x 2N), warp tile 32 x 64. 2 CTAs/SM.
// Fused branchless A+B loader (measured fastest). Prefetch after compute.
// MODE 1: fp32 out + bias + residual.
// MODE 2: QKV split -> q (pre-scaled by CEXP_CONST) / k fp16, V -> vT.
// ---------------------------------------------------------------------------
#define GP 16   // words per 32-half block row
#define A_BLK (128 * GP)
#define B_BLK (128 * GP)
#define STAGE (2 * (A_BLK + B_BLK))
#define GEMM_SMEM (3 * STAGE * 4)   // 98304 bytes

template <int MODE>
__global__ void __launch_bounds__(256, 2)
gemm_mma(const __half* __restrict__ A, const __half* __restrict__ BT,
         const float* __restrict__ bias, const float* __restrict__ res,
         float* __restrict__ Cout, __half* __restrict__ h2out,
         __half* __restrict__ vT, int N, int K) {
    extern __shared__ uint32_t smw[];
    uint32_t smb = smem_u32(smw);

    int tid = threadIdx.x, lane = tid & 31, wid = tid >> 5;
    int g = lane >> 2, c = lane & 3;
    int wm = wid & 3, wn = wid >> 2;
    int bm = blockIdx.y * 128, bn = blockIdx.x * 128;

    const __half* Ab = A + (size_t)bm * K;
    const __half* Bb = BT + (size_t)bn * K;

    int iters = K / 64;

    auto load_stage = [&](int s, int ko) {   // ko in halves
        uint32_t ab = smb + (uint32_t)(s * STAGE) * 4;
        uint32_t bb = ab + (uint32_t)(2 * A_BLK) * 4;
        #pragma unroll
        for (int i = 0; i < 4; i++) {
            int idx = tid + i * 256;
            int r = idx >> 3, j = idx & 7;
            int blk = j >> 2, jw = (j & 3) * 4;
            uint32_t so = (uint32_t)(blk * A_BLK + r * GP + jw) * 4;
            int kh = ko + blk * 32 + jw * 2;
            CP_ASYNC16(ab + so, Ab + (size_t)r * K + kh);
            CP_ASYNC16(bb + so, Bb + (size_t)r * K + kh);
        }
    };

    load_stage(0, 0);  CP_COMMIT();
    load_stage(1, 64); CP_COMMIT();

    float acc[2][8][4] = {};

    for (int it = 0; it < iters; ++it) {
        CP_WAIT(1);
        __syncthreads();

        const uint32_t* stg = smw + (it % 3) * STAGE;

        #pragma unroll
        for (int blk = 0; blk < 2; ++blk) {
            const uint32_t* As = stg + blk * A_BLK;
            const uint32_t* Bs = stg + 2 * A_BLK + blk * B_BLK;

            uint4 alo0 = *(const uint4*)&As[(wm * 32 + g) * GP + 4 * c];
            uint4 ahi0 = *(const uint4*)&As[(wm * 32 + g + 8) * GP + 4 * c];
            uint4 alo1 = *(const uint4*)&As[(wm * 32 + 16 + g) * GP + 4 * c];
            uint4 ahi1 = *(const uint4*)&As[(wm * 32 + 24 + g) * GP + 4 * c];

            #pragma unroll
            for (int nt = 0; nt < 8; ++nt) {
                uint4 bq = *(const uint4*)&Bs[(wn * 64 + nt * 8 + g) * GP + 4 * c];
                mma16(acc[0][nt], alo0.x, ahi0.x, alo0.y, ahi0.y, bq.x, bq.y);
                mma16(acc[0][nt], alo0.z, ahi0.z, alo0.w, ahi0.w, bq.z, bq.w);
                mma16(acc[1][nt], alo1.x, ahi1.x, alo1.y, ahi1.y, bq.x, bq.y);
                mma16(acc[1][nt], alo1.z, ahi1.z, alo1.w, ahi1.w, bq.z, bq.w);
            }
        }

        // prefetch AFTER compute (slot (it+2)%3 consumed at it-1; safe past
        // this iter's barrier)
        if (it + 2 < iters) load_stage((it + 2) % 3, (it + 2) * 64);
        CP_COMMIT();
    }

    #pragma unroll
    for (int mt = 0; mt < 2; ++mt) {
        int r = bm + wm * 32 + mt * 16 + g;
        #pragma unroll
        for (int nt = 0; nt < 8; ++nt) {
            int col = bn + wn * 64 + nt * 8 + 2 * c;
            float2 bi = *(const float2*)(bias + col);
            float2 o0 = {acc[mt][nt][0] + bi.x, acc[mt][nt][1] + bi.y};
            float2 o1 = {acc[mt][nt][2] + bi.x, acc[mt][nt][3] + bi.y};
            if (MODE == 1) {
                size_t i0 = (size_t)r * N + col;
                size_t i1 = (size_t)(r + 8) * N + col;
                float2 q0 = *(const float2*)(res + i0);
                float2 q1 = *(const float2*)(res + i1);
                o0.x += q0.x; o0.y += q0.y;
                o1.x += q1.x; o1.y += q1.y;
                *(float2*)(Cout + i0) = o0;
                *(float2*)(Cout + i1) = o1;
            } else {   // MODE 2: QKV split
                int cm = col % 192;
                if (cm >= 128) {
                    // V element: scatter fp16 to vT[(b,h)][d][t_perm]
                    int hh = col / 192, d = cm - 128;
                    int bi0 = r >> 11, tb = r & 2047;
                    int tg = tb - g;
                    int p0 = tg + 4 * (g >> 1) + (g & 1);
                    int p1 = p0 + 2;
                    size_t vb = ((size_t)(bi0 * N_HEAD + hh) * HD + d) * T_SEQ;
                    vT[vb + p0]         = __float2half(o0.x);
                    vT[vb + T_SEQ + p0] = __float2half(o0.y);
                    vT[vb + p1]         = __float2half(o1.x);
                    vT[vb + T_SEQ + p1] = __float2half(o1.y);
                } else {
                    if (cm < 64) {   // q: fold softmax scale * log2e
                        o0.x *= CEXP_CONST; o0.y *= CEXP_CONST;
                        o1.x *= CEXP_CONST; o1.y *= CEXP_CONST;
                    }
                    *(__half2*)(h2out + (size_t)r * QKV_DIM + col) =
                        __floats2half2_rn(o0.x, o0.y);
                    *(__half2*)(h2out + (size_t)(r + 8) * QKV_DIM + col) =
                        __floats2half2_rn(o1.x, o1.y);
                }
            }
        }
    }
}

// ---------------------------------------------------------------------------
// Flash attention — R15 structure, but Q FRAGMENTS LIVE IN REGISTERS:
// loaded once from gmem before the loop (16 regs/thread), Q smem deleted.
// Removes the Q cp.async stage, 24KB smem, and 4 LDS.128 per warp-iter.
// fp16 mma, cp.async 3-stage K/V ring, ONE barrier/iter, ones-mma row sums.
// CTA = 128 q-rows of one (b,h); 256 threads = 8 warps x 16 rows.
// q arrives pre-scaled by scale*log2e -> P = ex2(S) directly (f16x2 MUFU).
// V^T arrives 16-token-permuted (LDS.64 b-frags).
// ---------------------------------------------------------------------------
#define FPQW 48
#define FPVW 40
#define KVWW (64 * FPQW + 64 * FPVW)
#define FLASH_SMEM (3 * KVWW * 4)   // 67584 bytes

__global__ void __launch_bounds__(256, 2)
flash_mma(const __half* __restrict__ qkv, const __half* __restrict__ vTg,
          __half* __restrict__ out) {
    extern __shared__ uint32_t smw[];
    uint32_t smb = smem_u32(smw);

    int tid = threadIdx.x, lane = tid & 31, wid = tid >> 5;
    int g = lane >> 2, c = lane & 3;
    int rb = wid * 16;
    int m0 = blockIdx.x * 128;
    int h  = blockIdx.y;
    int bb = blockIdx.z;

    const __half* base = qkv + (size_t)bb * T_SEQ * QKV_DIM + h * (3 * HD);
    const __half* vbase = vTg + (size_t)(bb * N_HEAD + h) * HD * T_SEQ;

    auto load_kv = [&](int s, int n0) {
        uint32_t kb = smb + (uint32_t)(s * KVWW) * 4;
        uint32_t vb = kb + (uint32_t)(64 * FPQW) * 4;
        #pragma unroll
        for (int i = 0; i < 2; i++) {
            int idx = tid + i * 256;
            int r = idx >> 3, j = idx & 7;
            CP_ASYNC16(kb + (uint32_t)(r * FPQW + j * 4) * 4,
                       base + (size_t)(n0 + r) * QKV_DIM + 64 + j * 8);
            CP_ASYNC16(vb + (uint32_t)(r * FPVW + j * 4) * 4,
                       vbase + (size_t)r * T_SEQ + n0 + j * 8);
        }
    };

    load_kv(0, 0); CP_COMMIT();
    load_kv(1, 64); CP_COMMIT();

    // Q A-fragments straight from gmem (loop-invariant, 16B aligned):
    // blk b covers q halves b*32 + 8c .. +7 of rows m0+rb+g / +8.
    uint4 qf[4];
    {
        const __half* q0 = base + (size_t)(m0 + rb + g) * QKV_DIM + 8 * c;
        const __half* q1 = base + (size_t)(m0 + rb + g + 8) * QKV_DIM + 8 * c;
        qf[0] = *(const uint4*)(q0);        // blk0, row g
        qf[1] = *(const uint4*)(q1);        // blk0, row g+8
        qf[2] = *(const uint4*)(q0 + 32);   // blk1, row g
        qf[3] = *(const uint4*)(q1 + 32);   // blk1, row g+8
    }

    float o[8][4] = {};
    float osum[4] = {};   // ones-mma row-sum accumulator

    const int NT = T_SEQ / 64;   // 32 tiles
    for (int it = 0; it < NT; ++it) {
        CP_WAIT(1);
        __syncthreads();

        const uint32_t* Kw = smw + (it % 3) * KVWW;
        const uint32_t* Vw = Kw + 64 * FPQW;

        // ---- S = Q @ K^T : Q frags from registers, K LDS.128 ----
        float s[8][4] = {};
        #pragma unroll
        for (int blk = 0; blk < 2; ++blk) {
            int bo = blk * 16 + 4 * c;
            uint4 qlo = qf[blk * 2];
            uint4 qhi = qf[blk * 2 + 1];
            #pragma unroll
            for (int nt = 0; nt < 8; ++nt) {
                uint4 kq = *(const uint4*)&Kw[(nt * 8 + g) * FPQW + bo];
                mma16(s[nt], qlo.x, qhi.x, qlo.y, qhi.y, kq.x, kq.y);
                mma16(s[nt], qlo.z, qhi.z, qlo.w, qhi.w, kq.z, kq.w);
            }
        }

        // ---- P = ex2(S) in f16x2 (A-operand layout, no extra pack) ----
        uint32_t ph0[8], ph1[8];
        #pragma unroll
        for (int nt = 0; nt < 8; ++nt) {
            ph0[nt] = ex2h2(packh2(s[nt][0], s[nt][1]));
            ph1[nt] = ex2h2(packh2(s[nt][2], s[nt][3]));
        }

        // ---- O += P @ V; row sums += P @ ones (4 extra mma) ----
        #pragma unroll
        for (int kt = 0; kt < 4; ++kt) {
            uint32_t a0 = ph0[2 * kt];
            uint32_t a1 = ph1[2 * kt];
            uint32_t a2 = ph0[2 * kt + 1];
            uint32_t a3 = ph1[2 * kt + 1];
            int vw = kt * 8 + 2 * c;
            #pragma unroll
            for (int nt = 0; nt < 8; ++nt) {
                uint2 v = *(const uint2*)&Vw[(nt * 8 + g) * FPVW + vw];
                mma16(o[nt], a0, a1, a2, a3, v.x, v.y);
            }
            mma16(osum, a0, a1, a2, a3, H2_ONES, H2_ONES);
        }

        // prefetch tile it+2 into slot (it+2)%3 (freed at it-1)
        if (it + 2 < NT) load_kv((it + 2) % 3, (it + 2) * 64);
        CP_COMMIT();
    }

    // epilogue: osum[0]/osum[2] are FULL row sums (mma gathered the quad)
    float inv0 = 1.0f / osum[0];
    float inv1 = 1.0f / osum[2];
    int row0 = m0 + rb + g;
    int row1 = row0 + 8;
    __half* ob = out + (size_t)bb * T_SEQ * C_DIM + h * HD;
    #pragma unroll
    for (int nt = 0; nt < 8; ++nt) {
        int col = nt * 8 + 2 * c;
        *(__half2*)(ob + (size_t)row0 * C_DIM + col) =
            __floats2half2_rn(o[nt][0] * inv0, o[nt][1] * inv0);
        *(__half2*)(ob + (size_t)row1 * C_DIM + col) =
            __floats2half2_rn(o[nt][2] * inv1, o[nt][3] * inv1);
    }
}

// ---------------------------------------------------------------------------
// Launch
// ---------------------------------------------------------------------------
static void run_pass(const float* x_in, const float* ln_g, const float* ln_b,
                     const __half* wT, const float* b_attn,
                     const __half* wpT, const float* b_proj,
                     float* x_out,
                     __half* hbuf, __half* qkvbuf, __half* vTbuf,
                     __half* attbuf) {
    ln_kernel<<<M_TOK / 8, 256>>>(x_in, ln_g, ln_b, hbuf);

    dim3 gq(QKV_DIM / 128, M_TOK / 128);
    gemm_mma<2><<<gq, 256, GEMM_SMEM>>>(hbuf, wT, b_attn, nullptr,
                                        nullptr, qkvbuf, vTbuf,
                                        QKV_DIM, C_DIM);

    dim3 gf(T_SEQ / 128, N_HEAD, B_SZ);
    flash_mma<<<gf, 256, FLASH_SMEM>>>(qkvbuf, vTbuf, attbuf);

    dim3 gp(C_DIM / 128, M_TOK / 128);
    gemm_mma<1><<<gp, 256, GEMM_SMEM>>>(attbuf, wpT, b_proj, x_in,
                                        x_out, nullptr, nullptr,
                                        C_DIM, C_DIM);
}

extern "C" void kernel_launch(void* const* d_in, const int* in_sizes, int n_in,
                              void* d_out, int out_size) {
    const float* x      = (const float*)d_in[0];
    const float* w_attn = (const float*)d_in[1];
    const float* b_attn = (const float*)d_in[2];
    const float* w_proj = (const float*)d_in[3];
    const float* b_proj = (const float*)d_in[4];
    const float* ln1_g  = (const float*)d_in[5];
    const float* ln1_b  = (const float*)d_in[6];
    const float* ln2_g  = (const float*)d_in[7];
    const float* ln2_b  = (const float*)d_in[8];
    float* out = (float*)d_out;

    cudaFuncSetAttribute(flash_mma,
                         cudaFuncAttributeMaxDynamicSharedMemorySize, FLASH_SMEM);
    cudaFuncSetAttribute((const void*)gemm_mma<1>,
                         cudaFuncAttributeMaxDynamicSharedMemorySize, GEMM_SMEM);
    cudaFuncSetAttribute((const void*)gemm_mma<2>,
                         cudaFuncAttributeMaxDynamicSharedMemorySize, GEMM_SMEM);

    __half *hbuf, *qkvbuf, *vTbuf, *attbuf, *wT, *wpT;
    cudaGetSymbolAddress((void**)&hbuf, g_h16);
    cudaGetSymbolAddress((void**)&qkvbuf, g_qkv16);
    cudaGetSymbolAddress((void**)&vTbuf, g_vT16);
    cudaGetSymbolAddress((void**)&attbuf, g_att16);
    cudaGetSymbolAddress((void**)&wT, g_wT16);
    cudaGetSymbolAddress((void**)&wpT, g_wpT16);

    // Both weight transposes in one launch (z=0: w_attn, z=1: w_proj)
    dim3 tb(32, 8);
    dim3 tg(QKV_DIM / 32, C_DIM / 32, 2);
    transpose_both<<<tg, tb>>>(w_attn, wT, w_proj, wpT);

    run_pass(x, ln1_g, ln1_b, wT, b_attn, wpT, b_proj,
             out, hbuf, qkvbuf, vTbuf, attbuf);
    run_pass(out, ln2_g, ln2_b, wT, b_attn, wpT, b_proj,
             out, hbuf, qkvbuf, vTbuf, attbuf);
}